// round 13
// baseline (speedup 1.0000x reference)
#include <cuda_runtime.h>
#include <cuda_bf16.h>
#include <cstdint>

#define EDIM 1024
#define NH   16
#define HD   64
#define NB   4
#define SEQ  2048
#define MTOT (NB*SEQ)   // 8192 rows
#define SLOT ((size_t)MTOT * EDIM)
#define WSLOT ((size_t)EDIM * EDIM)

// ---------------------------------------------------------------------------
// Scratch: z-indexed split buffers.
// ---------------------------------------------------------------------------
__device__ __nv_bfloat16 g_xh[3 * SLOT];
__device__ __nv_bfloat16 g_xl[3 * SLOT];
__device__ __nv_bfloat16 g_ph[3 * SLOT];
__device__ __nv_bfloat16 g_pl[3 * SLOT];
__device__ __nv_bfloat16 g_wh[4 * WSLOT];
__device__ __nv_bfloat16 g_wl[4 * WSLOT];

// ---------------------------------------------------------------------------
// helpers
// ---------------------------------------------------------------------------
__device__ __forceinline__ uint32_t smem_u32(const void* p) {
    uint32_t a;
    asm("{ .reg .u64 t; cvta.to.shared.u64 t, %1; cvt.u32.u64 %0, t; }"
        : "=r"(a) : "l"(p));
    return a;
}

__device__ __forceinline__ void ldsm_x4(uint32_t* r, uint32_t addr) {
    asm volatile("ldmatrix.sync.aligned.m8n8.x4.shared.b16 {%0,%1,%2,%3}, [%4];"
                 : "=r"(r[0]), "=r"(r[1]), "=r"(r[2]), "=r"(r[3]) : "r"(addr));
}

__device__ __forceinline__ void ldsm_x4_t(uint32_t* r, uint32_t addr) {
    asm volatile("ldmatrix.sync.aligned.m8n8.x4.trans.shared.b16 {%0,%1,%2,%3}, [%4];"
                 : "=r"(r[0]), "=r"(r[1]), "=r"(r[2]), "=r"(r[3]) : "r"(addr));
}

__device__ __forceinline__ void mma16816(float* d, const uint32_t* a,
                                         const uint32_t* b) {
    asm volatile(
        "mma.sync.aligned.m16n8k16.row.col.f32.bf16.bf16.f32 "
        "{%0,%1,%2,%3}, {%4,%5,%6,%7}, {%8,%9}, {%0,%1,%2,%3};"
        : "+f"(d[0]), "+f"(d[1]), "+f"(d[2]), "+f"(d[3])
        : "r"(a[0]), "r"(a[1]), "r"(a[2]), "r"(a[3]), "r"(b[0]), "r"(b[1]));
}

__device__ __forceinline__ void cp16(uint32_t smem_dst, const void* gptr) {
    asm volatile("cp.async.cg.shared.global [%0], [%1], 16;"
                 :: "r"(smem_dst), "l"(gptr));
}
#define CP_COMMIT() asm volatile("cp.async.commit_group;")
#define CP_WAIT(n)  asm volatile("cp.async.wait_group %0;" :: "n"(n))

__device__ __forceinline__ float ex2f(float x) {
    float y;
    asm("ex2.approx.f32 %0, %1;" : "=f"(y) : "f"(x));
    return y;
}

__device__ __forceinline__ void split_pair(float x, float y,
                                           uint32_t& hi, uint32_t& lo) {
    __nv_bfloat16 hx = __float2bfloat16_rn(x);
    __nv_bfloat16 hy = __float2bfloat16_rn(y);
    __nv_bfloat162 h2 = __halves2bfloat162(hx, hy);
    __nv_bfloat162 l2 = __halves2bfloat162(
        __float2bfloat16_rn(x - __bfloat162float(hx)),
        __float2bfloat16_rn(y - __bfloat162float(hy)));
    hi = *reinterpret_cast<uint32_t*>(&h2);
    lo = *reinterpret_cast<uint32_t*>(&l2);
}

// ---------------------------------------------------------------------------
// split passes (z-indexed)
// ---------------------------------------------------------------------------
__global__ void split_in_kernel(const float* __restrict__ q, const float* __restrict__ k,
                                const float* __restrict__ v,
                                __nv_bfloat16* __restrict__ oh,
                                __nv_bfloat16* __restrict__ ol, int n4)
{
    int z = blockIdx.y;
    const float* x = (z == 0) ? q : (z == 1) ? k : v;
    oh += (size_t)z * SLOT;
    ol += (size_t)z * SLOT;
    int i = blockIdx.x * blockDim.x + threadIdx.x;
    if (i >= n4) return;
    float4 vv = reinterpret_cast<const float4*>(x)[i];
    uint32_t h0, l0, h1, l1;
    split_pair(vv.x, vv.y, h0, l0);
    split_pair(vv.z, vv.w, h1, l1);
    reinterpret_cast<uint2*>(oh)[i] = make_uint2(h0, h1);
    reinterpret_cast<uint2*>(ol)[i] = make_uint2(l0, l1);
}

__global__ void split_w_kernel(const float* __restrict__ w0, const float* __restrict__ w1,
                               const float* __restrict__ w2, const float* __restrict__ w3,
                               __nv_bfloat16* __restrict__ oh,
                               __nv_bfloat16* __restrict__ ol, int n4)
{
    int z = blockIdx.y;
    const float* x = (z == 0) ? w0 : (z == 1) ? w1 : (z == 2) ? w2 : w3;
    oh += (size_t)z * WSLOT;
    ol += (size_t)z * WSLOT;
    int i = blockIdx.x * blockDim.x + threadIdx.x;
    if (i >= n4) return;
    float4 vv = reinterpret_cast<const float4*>(x)[i];
    uint32_t h0, l0, h1, l1;
    split_pair(vv.x, vv.y, h0, l0);
    split_pair(vv.z, vv.w, h1, l1);
    reinterpret_cast<uint2*>(oh)[i] = make_uint2(h0, h1);
    reinterpret_cast<uint2*>(ol)[i] = make_uint2(l0, l1);
}

// ---------------------------------------------------------------------------
// HMMA GEMM: C = A * W^T, 3 products, pre-split bf16.
// CTA tile 128x128, BK=16, 256 threads, 8 warps (2m x 4n, warp tile 64x32),
// 4-stage cp.async ring, one barrier per stage, 2 CTAs/SM
// -> 4 warps per SMSP for latency cover.
// For SPLIT_OUT with z==0 (q projection), output pre-scaled by log2(e).
// ---------------------------------------------------------------------------
#define ROWB        48
#define TILEB       (128 * ROWB)         // 6144
#define STAGEB      (4 * TILEB)          // 24576
#define GEMM_STAGES 4
#define GEMM_SMEM   (GEMM_STAGES * STAGEB)   // 98304

template<bool SPLIT_OUT>
__global__ __launch_bounds__(256, 2)
void gemm_hmma(const __nv_bfloat16* __restrict__ Ah, const __nv_bfloat16* __restrict__ Al,
               const __nv_bfloat16* __restrict__ Wh, const __nv_bfloat16* __restrict__ Wl,
               const float* __restrict__ bias,
               float* __restrict__ C,
               __nv_bfloat16* __restrict__ Ch, __nv_bfloat16* __restrict__ Cl)
{
    extern __shared__ char smem[];
    const uint32_t sb = smem_u32(smem);
    const int tid  = threadIdx.x;
    const int wid  = tid >> 5;
    const int lane = tid & 31;
    const int row0 = blockIdx.y * 128;
    const int col0 = blockIdx.x * 128;
    const int z    = blockIdx.z;
    const int warp_m = (wid & 1) * 64;     // 0 or 64
    const int warp_n = (wid >> 1) * 32;    // 0,32,64,96

    Ah += (size_t)z * SLOT;  Al += (size_t)z * SLOT;
    Wh += (size_t)z * WSLOT; Wl += (size_t)z * WSLOT;

    const float oscale = (SPLIT_OUT && z == 0) ? 1.4426950408889634f : 1.0f;

    const uint32_t a_loff = (uint32_t)(lane & 15) * ROWB + ((lane & 16) ? 16u : 0u);
    const uint32_t b_loff = (uint32_t)((lane & 7) + ((lane & 16) ? 8 : 0)) * ROWB
                          + ((lane & 8) ? 16u : 0u);

    auto issue_stage = [&](int s) {
        const uint32_t base = sb + (uint32_t)(s & 3) * STAGEB;
#pragma unroll
        for (int it = 0; it < 2; it++) {
            int c = tid + it * 256;            // 0..511 : A chunks
            int row = c >> 2, q = c & 3;
            int sp = q >> 1, ch = q & 1;
            uint32_t dst = base + (uint32_t)sp * TILEB
                         + (uint32_t)row * ROWB + (uint32_t)ch * 16;
            const __nv_bfloat16* src = (sp ? Al : Ah)
                + (size_t)(row0 + row) * EDIM + s * 16 + ch * 8;
            cp16(dst, src);
        }
#pragma unroll
        for (int it = 0; it < 2; it++) {
            int c = tid + it * 256;            // 0..511 : B chunks
            int row = c >> 2, q = c & 3;
            int sp = q >> 1, ch = q & 1;
            uint32_t dst = base + (uint32_t)(2 + sp) * TILEB
                         + (uint32_t)row * ROWB + (uint32_t)ch * 16;
            const __nv_bfloat16* src = (sp ? Wl : Wh)
                + (size_t)(col0 + row) * EDIM + s * 16 + ch * 8;
            cp16(dst, src);
        }
        CP_COMMIT();
    };

    issue_stage(0);
    issue_stage(1);
    issue_stage(2);

    float acc[4][4][4];
#pragma unroll
    for (int mt = 0; mt < 4; mt++)
#pragma unroll
        for (int nt = 0; nt < 4; nt++)
#pragma unroll
            for (int i = 0; i < 4; i++) acc[mt][nt][i] = 0.f;

    const int NKT = EDIM / 16;   // 64
    for (int s = 0; s < NKT; s++) {
        if (s + 3 <= NKT) { CP_WAIT(2); }
        else if (s + 2 <= NKT) { CP_WAIT(1); }
        else { CP_WAIT(0); }
        __syncthreads();
        if (s + 3 < NKT) issue_stage(s + 3);   // target consumed at s-1: safe

        const uint32_t base = sb + (uint32_t)(s & 3) * STAGEB;
        uint32_t afr[2][4][4];
#pragma unroll
        for (int sp = 0; sp < 2; sp++)
#pragma unroll
            for (int mt = 0; mt < 4; mt++)
                ldsm_x4(afr[sp][mt],
                        base + sp * TILEB + (uint32_t)(warp_m + mt * 16) * ROWB + a_loff);
#pragma unroll
        for (int grp = 0; grp < 2; grp++) {
            uint32_t bh[4], bl[4];
            uint32_t bb = base + (uint32_t)(warp_n + grp * 16) * ROWB + b_loff;
            ldsm_x4(bh, bb + 2 * TILEB);
            ldsm_x4(bl, bb + 3 * TILEB);
#pragma unroll
            for (int mt = 0; mt < 4; mt++) {
                mma16816(acc[mt][grp * 2 + 0], afr[0][mt], &bh[0]);
                mma16816(acc[mt][grp * 2 + 1], afr[0][mt], &bh[2]);
                mma16816(acc[mt][grp * 2 + 0], afr[0][mt], &bl[0]);
                mma16816(acc[mt][grp * 2 + 1], afr[0][mt], &bl[2]);
                mma16816(acc[mt][grp * 2 + 0], afr[1][mt], &bh[0]);
                mma16816(acc[mt][grp * 2 + 1], afr[1][mt], &bh[2]);
            }
        }
    }

    const int g   = lane >> 2;
    const int tig = lane & 3;
#pragma unroll
    for (int mt = 0; mt < 4; mt++) {
        int r = row0 + warp_m + mt * 16 + g;
#pragma unroll
        for (int nt = 0; nt < 4; nt++) {
            int col = col0 + warp_n + nt * 8 + 2 * tig;
            if (SPLIT_OUT) {
                uint32_t hw, lw;
                split_pair(acc[mt][nt][0] * oscale, acc[mt][nt][1] * oscale, hw, lw);
                *(uint32_t*)(Ch + (size_t)z * SLOT + (size_t)r * EDIM + col) = hw;
                *(uint32_t*)(Cl + (size_t)z * SLOT + (size_t)r * EDIM + col) = lw;
                split_pair(acc[mt][nt][2] * oscale, acc[mt][nt][3] * oscale, hw, lw);
                *(uint32_t*)(Ch + (size_t)z * SLOT + (size_t)(r + 8) * EDIM + col) = hw;
                *(uint32_t*)(Cl + (size_t)z * SLOT + (size_t)(r + 8) * EDIM + col) = lw;
            } else {
                float bx = bias[col], by = bias[col + 1];
                *(float2*)(C + (size_t)r * EDIM + col) =
                    make_float2(acc[mt][nt][0] + bx, acc[mt][nt][1] + by);
                *(float2*)(C + (size_t)(r + 8) * EDIM + col) =
                    make_float2(acc[mt][nt][2] + bx, acc[mt][nt][3] + by);
            }
        }
    }
}

// ---------------------------------------------------------------------------
// Flash attention on HMMA. 4 warps x 32 q-rows (Br=128), Bc=64, fused
// per-16-key block, 3-stage ring, 2 CTAs/SM.
// q PRE-SCALED by log2(e) in projection epilogue -> raw ex2.approx here;
// softmax over UNSCALED scores (faithful reference bug), no running max.
// Row sums computed BY THE TENSOR CORE: an all-ones B operand appended to
// the PV phase accumulates sum_k P[row][k] in fp32 (no FADD chain, no
// shuffles — every lane of a row-quad holds the row sum directly).
// ---------------------------------------------------------------------------
#define KROWB    144
#define KTILE    (64 * KROWB)                // 9216
#define QTILE    (128 * KROWB)               // 18432
#define FA_STAGE (4 * KTILE)                 // 36864
#define FA_STAGES 3
#define FA_SMEM  (FA_STAGES * FA_STAGE)      // 110592

__global__ __launch_bounds__(128, 2)
void flash_hmma(const __nv_bfloat16* __restrict__ ph, const __nv_bfloat16* __restrict__ pl,
                __nv_bfloat16* __restrict__ oh, __nv_bfloat16* __restrict__ ol)
{
    extern __shared__ char sm[];
    const uint32_t sb = smem_u32(sm);
    const int tid  = threadIdx.x;
    const int wid  = tid >> 5;
    const int lane = tid & 31;
    const int warp_m = wid * 32;

    const int qt = blockIdx.x;
    const int h  = blockIdx.y;
    const int b  = blockIdx.z;
    const size_t baseRow = (size_t)b * SEQ;
    const int hcol = h * HD;

    const __nv_bfloat16* qh = ph;
    const __nv_bfloat16* ql = pl;
    const __nv_bfloat16* kh = ph + SLOT;
    const __nv_bfloat16* kl = pl + SLOT;
    const __nv_bfloat16* vh = ph + 2 * SLOT;
    const __nv_bfloat16* vl = pl + 2 * SLOT;

    const uint32_t a_loff  = (uint32_t)(lane & 15) * KROWB + ((lane & 16) ? 16u : 0u);
    const uint32_t bk_loff = (uint32_t)((lane & 7) + ((lane & 16) ? 8 : 0)) * KROWB
                           + ((lane & 8) ? 16u : 0u);
    const uint32_t bv_loff = (uint32_t)((lane & 7) + ((lane & 8) ? 8 : 0)) * KROWB
                           + ((lane & 16) ? 16u : 0u);

    // ---- stage Q (hi at 0, lo at QTILE), pull A-fragments ----
    {
#pragma unroll
        for (int it = 0; it < 8; it++) {
            int c = tid + it * 128;          // 0..1023
            int row = c >> 3, ch = c & 7;
            uint32_t doff = (uint32_t)row * KROWB + (uint32_t)ch * 16;
            size_t ga = (baseRow + qt * 128 + row) * EDIM + hcol + ch * 8;
            cp16(sb + doff,         qh + ga);
            cp16(sb + QTILE + doff, ql + ga);
        }
        CP_COMMIT();
        CP_WAIT(0);
        __syncthreads();
    }
    uint32_t qfr[2][4][2][4];   // [split][kstep][mt][frag]
#pragma unroll
    for (int sp = 0; sp < 2; sp++)
#pragma unroll
        for (int ks = 0; ks < 4; ks++)
#pragma unroll
            for (int mt = 0; mt < 2; mt++)
                ldsm_x4(qfr[sp][ks][mt],
                        sb + sp * QTILE + (uint32_t)(warp_m + mt * 16) * KROWB
                             + ks * 32 + a_loff);
    __syncthreads();

    auto issue_kv = [&](int t) {
        const uint32_t base = sb + (uint32_t)(t % 3) * FA_STAGE;
#pragma unroll
        for (int it = 0; it < 4; it++) {
            int c = tid + it * 128;          // 0..511
            int row = c >> 3, ch = c & 7;
            uint32_t doff = (uint32_t)row * KROWB + (uint32_t)ch * 16;
            size_t ga = (baseRow + t * 64 + row) * EDIM + hcol + ch * 8;
            cp16(base + doff,             kh + ga);
            cp16(base + KTILE + doff,     kl + ga);
            cp16(base + 2 * KTILE + doff, vh + ga);
            cp16(base + 3 * KTILE + doff, vl + ga);
        }
        CP_COMMIT();
    };

    issue_kv(0);
    issue_kv(1);

    float Oa[2][8][4];
#pragma unroll
    for (int mt = 0; mt < 2; mt++)
#pragma unroll
        for (int i = 0; i < 8; i++)
#pragma unroll
            for (int c = 0; c < 4; c++) Oa[mt][i][c] = 0.f;
    float Osum[2][4];           // tensor-core row sums (cols all-equal)
#pragma unroll
    for (int mt = 0; mt < 2; mt++)
#pragma unroll
        for (int c = 0; c < 4; c++) Osum[mt][c] = 0.f;

    const uint32_t onesb[2] = {0x3F803F80u, 0x3F803F80u};  // bf16 1.0 x2

    const int NT = SEQ / 64;   // 32
    for (int t = 0; t < NT; t++) {
        if (t + 2 <= NT) { CP_WAIT(1); } else { CP_WAIT(0); }
        __syncthreads();
        if (t + 2 < NT) issue_kv(t + 2);

        const uint32_t bs = sb + (uint32_t)(t % 3) * FA_STAGE;

        // fused per-16-key block: QK -> ex2 -> pack -> PV (+ones sum)
#pragma unroll
        for (int ng = 0; ng < 4; ng++) {
            float S[2][2][4];
#pragma unroll
            for (int mt = 0; mt < 2; mt++)
#pragma unroll
                for (int tt = 0; tt < 2; tt++)
#pragma unroll
                    for (int c = 0; c < 4; c++) S[mt][tt][c] = 0.f;

#pragma unroll
            for (int ks = 0; ks < 4; ks++) {
                uint32_t b1[4], b2[4];
                uint32_t kb = bs + (uint32_t)(ng * 16) * KROWB + ks * 32 + bk_loff;
                ldsm_x4(b1, kb);
                ldsm_x4(b2, kb + KTILE);
#pragma unroll
                for (int mt = 0; mt < 2; mt++) {
                    mma16816(S[mt][0], qfr[0][ks][mt], &b1[0]);
                    mma16816(S[mt][1], qfr[0][ks][mt], &b1[2]);
                    mma16816(S[mt][0], qfr[0][ks][mt], &b2[0]);
                    mma16816(S[mt][1], qfr[0][ks][mt], &b2[2]);
                    mma16816(S[mt][0], qfr[1][ks][mt], &b1[0]);
                    mma16816(S[mt][1], qfr[1][ks][mt], &b1[2]);
                }
            }

            uint32_t p1[2][4], p2[2][4];
#pragma unroll
            for (int mt = 0; mt < 2; mt++) {
#pragma unroll
                for (int tt = 0; tt < 2; tt++) {
                    S[mt][tt][0] = ex2f(S[mt][tt][0]);
                    S[mt][tt][1] = ex2f(S[mt][tt][1]);
                    S[mt][tt][2] = ex2f(S[mt][tt][2]);
                    S[mt][tt][3] = ex2f(S[mt][tt][3]);
                }
#pragma unroll
                for (int tt = 0; tt < 2; tt++)
#pragma unroll
                    for (int hl = 0; hl < 2; hl++)
                        split_pair(S[mt][tt][2 * hl + 0], S[mt][tt][2 * hl + 1],
                                   p1[mt][tt * 2 + hl], p2[mt][tt * 2 + hl]);
                // row sums via tensor core (ones operand, no ldsm needed)
                mma16816(Osum[mt], p1[mt], onesb);
                mma16816(Osum[mt], p2[mt], onesb);
            }

#pragma unroll
            for (int dg = 0; dg < 4; dg++) {
                uint32_t v1[4], v2[4];
                uint32_t vb = bs + 2 * KTILE + (uint32_t)(ng * 16) * KROWB
                            + dg * 32 + bv_loff;
                ldsm_x4_t(v1, vb);
                ldsm_x4_t(v2, vb + KTILE);
#pragma unroll
                for (int mt = 0; mt < 2; mt++) {
                    mma16816(Oa[mt][dg * 2 + 0], p1[mt], &v1[0]);
                    mma16816(Oa[mt][dg * 2 + 1], p1[mt], &v1[2]);
                    mma16816(Oa[mt][dg * 2 + 0], p1[mt], &v2[0]);
                    mma16816(Oa[mt][dg * 2 + 1], p1[mt], &v2[2]);
                    mma16816(Oa[mt][dg * 2 + 0], p2[mt], &v1[0]);
                    mma16816(Oa[mt][dg * 2 + 1], p2[mt], &v1[2]);
                }
            }
        }
    }

    // ---- normalize & write split output into slot 0 of (oh, ol) ----
    // Osum[mt][0] = row (warp_m+mt*16+g) sum; Osum[mt][2] = row (+8) sum.
    const int g   = lane >> 2;
    const int tq2 = (lane & 3) * 2;
#pragma unroll
    for (int mt = 0; mt < 2; mt++) {
        const float inv0 = 1.0f / Osum[mt][0];
        const float inv1 = 1.0f / Osum[mt][2];
        const size_t r0 = (baseRow + qt * 128 + warp_m + mt * 16 + g) * EDIM + hcol;
        const size_t r1 = r0 + (size_t)8 * EDIM;
#pragma unroll
        for (int i = 0; i < 8; i++) {
            int d = i * 8 + tq2;
            uint32_t hw, lw;
            split_pair(Oa[mt][i][0] * inv0, Oa[mt][i][1] * inv0, hw, lw);
            *(uint32_t*)(oh + r0 + d) = hw;
            *(uint32_t*)(ol + r0 + d) = lw;
            split_pair(Oa[mt][i][2] * inv1, Oa[mt][i][3] * inv1, hw, lw);
            *(uint32_t*)(oh + r1 + d) = hw;
            *(uint32_t*)(ol + r1 + d) = lw;
        }
    }
}

// ---------------------------------------------------------------------------
extern "C" void kernel_launch(void* const* d_in, const int* in_sizes, int n_in,
                              void* d_out, int out_size)
{
    (void)in_sizes; (void)n_in; (void)out_size;

    const float* Q  = (const float*)d_in[0];
    const float* K  = (const float*)d_in[1];
    const float* V  = (const float*)d_in[2];
    const float* Wq = (const float*)d_in[3];
    const float* Wk = (const float*)d_in[4];
    const float* Wv = (const float*)d_in[5];
    const float* Wo = (const float*)d_in[6];
    const float* bo = (const float*)d_in[7];
    float* out = (float*)d_out;

    __nv_bfloat16 *xh, *xl, *phb, *plb, *wh, *wl;
    cudaGetSymbolAddress((void**)&xh, g_xh);
    cudaGetSymbolAddress((void**)&xl, g_xl);
    cudaGetSymbolAddress((void**)&phb, g_ph);
    cudaGetSymbolAddress((void**)&plb, g_pl);
    cudaGetSymbolAddress((void**)&wh, g_wh);
    cudaGetSymbolAddress((void**)&wl, g_wl);

    cudaFuncSetAttribute(gemm_hmma<true>,
                         cudaFuncAttributeMaxDynamicSharedMemorySize, GEMM_SMEM);
    cudaFuncSetAttribute(gemm_hmma<false>,
                         cudaFuncAttributeMaxDynamicSharedMemorySize, GEMM_SMEM);
    cudaFuncSetAttribute(flash_hmma,
                         cudaFuncAttributeMaxDynamicSharedMemorySize, FA_SMEM);

    const int nA4 = MTOT * EDIM / 4;
    const int nW4 = EDIM * EDIM / 4;

    split_in_kernel<<<dim3(nA4 / 256, 3), 256>>>(Q, K, V, xh, xl, nA4);
    split_w_kernel<<<dim3(nW4 / 256, 4), 256>>>(Wq, Wk, Wv, Wo, wh, wl, nW4);

    gemm_hmma<true><<<dim3(EDIM / 128, MTOT / 128, 3), 256, GEMM_SMEM>>>(
        xh, xl, wh, wl, nullptr, nullptr, phb, plb);

    flash_hmma<<<dim3(SEQ / 128, NH, NB), 128, FA_SMEM>>>(phb, plb, xh, xl);

    gemm_hmma<false><<<dim3(EDIM / 128, MTOT / 128, 1), 256, GEMM_SMEM>>>(
        xh, xl, wh + 3 * WSLOT, wl + 3 * WSLOT, bo, out, nullptr, nullptr);
}

// round 14
// speedup vs baseline: 1.1004x; 1.1004x over previous
#include <cuda_runtime.h>
#include <cuda_bf16.h>
#include <cstdint>

#define EDIM 1024
#define NH   16
#define HD   64
#define NB   4
#define SEQ  2048
#define MTOT (NB*SEQ)   // 8192 rows
#define SLOT ((size_t)MTOT * EDIM)
#define WSLOT ((size_t)EDIM * EDIM)

// ---------------------------------------------------------------------------
// Scratch: z-indexed split buffers.
// ---------------------------------------------------------------------------
__device__ __nv_bfloat16 g_xh[3 * SLOT];
__device__ __nv_bfloat16 g_xl[3 * SLOT];
__device__ __nv_bfloat16 g_ph[3 * SLOT];
__device__ __nv_bfloat16 g_pl[3 * SLOT];
__device__ __nv_bfloat16 g_wh[4 * WSLOT];
__device__ __nv_bfloat16 g_wl[4 * WSLOT];

// ---------------------------------------------------------------------------
// helpers
// ---------------------------------------------------------------------------
__device__ __forceinline__ uint32_t smem_u32(const void* p) {
    uint32_t a;
    asm("{ .reg .u64 t; cvta.to.shared.u64 t, %1; cvt.u32.u64 %0, t; }"
        : "=r"(a) : "l"(p));
    return a;
}

__device__ __forceinline__ void ldsm_x4(uint32_t* r, uint32_t addr) {
    asm volatile("ldmatrix.sync.aligned.m8n8.x4.shared.b16 {%0,%1,%2,%3}, [%4];"
                 : "=r"(r[0]), "=r"(r[1]), "=r"(r[2]), "=r"(r[3]) : "r"(addr));
}

__device__ __forceinline__ void ldsm_x4_t(uint32_t* r, uint32_t addr) {
    asm volatile("ldmatrix.sync.aligned.m8n8.x4.trans.shared.b16 {%0,%1,%2,%3}, [%4];"
                 : "=r"(r[0]), "=r"(r[1]), "=r"(r[2]), "=r"(r[3]) : "r"(addr));
}

__device__ __forceinline__ void mma16816(float* d, const uint32_t* a,
                                         const uint32_t* b) {
    asm volatile(
        "mma.sync.aligned.m16n8k16.row.col.f32.bf16.bf16.f32 "
        "{%0,%1,%2,%3}, {%4,%5,%6,%7}, {%8,%9}, {%0,%1,%2,%3};"
        : "+f"(d[0]), "+f"(d[1]), "+f"(d[2]), "+f"(d[3])
        : "r"(a[0]), "r"(a[1]), "r"(a[2]), "r"(a[3]), "r"(b[0]), "r"(b[1]));
}

__device__ __forceinline__ void cp16(uint32_t smem_dst, const void* gptr) {
    asm volatile("cp.async.cg.shared.global [%0], [%1], 16;"
                 :: "r"(smem_dst), "l"(gptr));
}
#define CP_COMMIT() asm volatile("cp.async.commit_group;")
#define CP_WAIT(n)  asm volatile("cp.async.wait_group %0;" :: "n"(n))

__device__ __forceinline__ float ex2f(float x) {
    float y;
    asm("ex2.approx.f32 %0, %1;" : "=f"(y) : "f"(x));
    return y;
}

__device__ __forceinline__ void split_pair(float x, float y,
                                           uint32_t& hi, uint32_t& lo) {
    __nv_bfloat16 hx = __float2bfloat16_rn(x);
    __nv_bfloat16 hy = __float2bfloat16_rn(y);
    __nv_bfloat162 h2 = __halves2bfloat162(hx, hy);
    __nv_bfloat162 l2 = __halves2bfloat162(
        __float2bfloat16_rn(x - __bfloat162float(hx)),
        __float2bfloat16_rn(y - __bfloat162float(hy)));
    hi = *reinterpret_cast<uint32_t*>(&h2);
    lo = *reinterpret_cast<uint32_t*>(&l2);
}

// ---------------------------------------------------------------------------
// split passes (z-indexed)
// ---------------------------------------------------------------------------
__global__ void split_in_kernel(const float* __restrict__ q, const float* __restrict__ k,
                                const float* __restrict__ v,
                                __nv_bfloat16* __restrict__ oh,
                                __nv_bfloat16* __restrict__ ol, int n4)
{
    int z = blockIdx.y;
    const float* x = (z == 0) ? q : (z == 1) ? k : v;
    oh += (size_t)z * SLOT;
    ol += (size_t)z * SLOT;
    int i = blockIdx.x * blockDim.x + threadIdx.x;
    if (i >= n4) return;
    float4 vv = reinterpret_cast<const float4*>(x)[i];
    uint32_t h0, l0, h1, l1;
    split_pair(vv.x, vv.y, h0, l0);
    split_pair(vv.z, vv.w, h1, l1);
    reinterpret_cast<uint2*>(oh)[i] = make_uint2(h0, h1);
    reinterpret_cast<uint2*>(ol)[i] = make_uint2(l0, l1);
}

__global__ void split_w_kernel(const float* __restrict__ w0, const float* __restrict__ w1,
                               const float* __restrict__ w2, const float* __restrict__ w3,
                               __nv_bfloat16* __restrict__ oh,
                               __nv_bfloat16* __restrict__ ol, int n4)
{
    int z = blockIdx.y;
    const float* x = (z == 0) ? w0 : (z == 1) ? w1 : (z == 2) ? w2 : w3;
    oh += (size_t)z * WSLOT;
    ol += (size_t)z * WSLOT;
    int i = blockIdx.x * blockDim.x + threadIdx.x;
    if (i >= n4) return;
    float4 vv = reinterpret_cast<const float4*>(x)[i];
    uint32_t h0, l0, h1, l1;
    split_pair(vv.x, vv.y, h0, l0);
    split_pair(vv.z, vv.w, h1, l1);
    reinterpret_cast<uint2*>(oh)[i] = make_uint2(h0, h1);
    reinterpret_cast<uint2*>(ol)[i] = make_uint2(l0, l1);
}

// ---------------------------------------------------------------------------
// HMMA GEMM (R12 configuration — measured best): C = A * W^T, 3 products.
// CTA tile 128x128, BK=16, 4 warps (warp tile 64x64), 128 threads,
// 4-stage cp.async ring, one barrier per stage, 2 CTAs/SM.
// For SPLIT_OUT with z==0 (q projection), output pre-scaled by log2(e).
// ---------------------------------------------------------------------------
#define ROWB        48
#define TILEB       (128 * ROWB)         // 6144
#define STAGEB      (4 * TILEB)          // 24576
#define GEMM_STAGES 4
#define GEMM_SMEM   (GEMM_STAGES * STAGEB)   // 98304

template<bool SPLIT_OUT>
__global__ __launch_bounds__(128, 2)
void gemm_hmma(const __nv_bfloat16* __restrict__ Ah, const __nv_bfloat16* __restrict__ Al,
               const __nv_bfloat16* __restrict__ Wh, const __nv_bfloat16* __restrict__ Wl,
               const float* __restrict__ bias,
               float* __restrict__ C,
               __nv_bfloat16* __restrict__ Ch, __nv_bfloat16* __restrict__ Cl)
{
    extern __shared__ char smem[];
    const uint32_t sb = smem_u32(smem);
    const int tid  = threadIdx.x;
    const int wid  = tid >> 5;
    const int lane = tid & 31;
    const int row0 = blockIdx.y * 128;
    const int col0 = blockIdx.x * 128;
    const int z    = blockIdx.z;
    const int warp_m = (wid & 1) * 64;
    const int warp_n = (wid >> 1) * 64;

    Ah += (size_t)z * SLOT;  Al += (size_t)z * SLOT;
    Wh += (size_t)z * WSLOT; Wl += (size_t)z * WSLOT;

    const float oscale = (SPLIT_OUT && z == 0) ? 1.4426950408889634f : 1.0f;

    const uint32_t a_loff = (uint32_t)(lane & 15) * ROWB + ((lane & 16) ? 16u : 0u);
    const uint32_t b_loff = (uint32_t)((lane & 7) + ((lane & 16) ? 8 : 0)) * ROWB
                          + ((lane & 8) ? 16u : 0u);

    auto issue_stage = [&](int s) {
        const uint32_t base = sb + (uint32_t)(s & 3) * STAGEB;
#pragma unroll
        for (int it = 0; it < 2; it++) {
            int c = tid + it * 128;            // 0..255
            int row = c >> 1, c16 = c & 1;
            uint32_t doff = (uint32_t)row * ROWB + (uint32_t)c16 * 16;
            size_t ga = (size_t)(row0 + row) * EDIM + s * 16 + c16 * 8;
            size_t gw = (size_t)(col0 + row) * EDIM + s * 16 + c16 * 8;
            cp16(base + doff,             Ah + ga);
            cp16(base + TILEB + doff,     Al + ga);
            cp16(base + 2 * TILEB + doff, Wh + gw);
            cp16(base + 3 * TILEB + doff, Wl + gw);
        }
        CP_COMMIT();
    };

    issue_stage(0);
    issue_stage(1);
    issue_stage(2);

    float acc[4][8][4];
#pragma unroll
    for (int mt = 0; mt < 4; mt++)
#pragma unroll
        for (int nt = 0; nt < 8; nt++)
#pragma unroll
            for (int i = 0; i < 4; i++) acc[mt][nt][i] = 0.f;

    const int NKT = EDIM / 16;   // 64
    for (int s = 0; s < NKT; s++) {
        if (s + 3 <= NKT) { CP_WAIT(2); }
        else if (s + 2 <= NKT) { CP_WAIT(1); }
        else { CP_WAIT(0); }
        __syncthreads();
        if (s + 3 < NKT) issue_stage(s + 3);   // target consumed at s-1: safe

        const uint32_t base = sb + (uint32_t)(s & 3) * STAGEB;
        uint32_t afr[2][4][4];
#pragma unroll
        for (int sp = 0; sp < 2; sp++)
#pragma unroll
            for (int mt = 0; mt < 4; mt++)
                ldsm_x4(afr[sp][mt],
                        base + sp * TILEB + (uint32_t)(warp_m + mt * 16) * ROWB + a_loff);
#pragma unroll
        for (int np = 0; np < 4; np++) {
            uint32_t bh[4], bl[4];
            uint32_t bb = base + (uint32_t)(warp_n + np * 16) * ROWB + b_loff;
            ldsm_x4(bh, bb + 2 * TILEB);
            ldsm_x4(bl, bb + 3 * TILEB);
#pragma unroll
            for (int mt = 0; mt < 4; mt++) {
                mma16816(acc[mt][2 * np + 0], afr[0][mt], &bh[0]);
                mma16816(acc[mt][2 * np + 1], afr[0][mt], &bh[2]);
                mma16816(acc[mt][2 * np + 0], afr[0][mt], &bl[0]);
                mma16816(acc[mt][2 * np + 1], afr[0][mt], &bl[2]);
                mma16816(acc[mt][2 * np + 0], afr[1][mt], &bh[0]);
                mma16816(acc[mt][2 * np + 1], afr[1][mt], &bh[2]);
            }
        }
    }

    const int g   = lane >> 2;
    const int tig = lane & 3;
#pragma unroll
    for (int mt = 0; mt < 4; mt++) {
        int r = row0 + warp_m + mt * 16 + g;
#pragma unroll
        for (int nt = 0; nt < 8; nt++) {
            int col = col0 + warp_n + nt * 8 + 2 * tig;
            if (SPLIT_OUT) {
                uint32_t hw, lw;
                split_pair(acc[mt][nt][0] * oscale, acc[mt][nt][1] * oscale, hw, lw);
                *(uint32_t*)(Ch + (size_t)z * SLOT + (size_t)r * EDIM + col) = hw;
                *(uint32_t*)(Cl + (size_t)z * SLOT + (size_t)r * EDIM + col) = lw;
                split_pair(acc[mt][nt][2] * oscale, acc[mt][nt][3] * oscale, hw, lw);
                *(uint32_t*)(Ch + (size_t)z * SLOT + (size_t)(r + 8) * EDIM + col) = hw;
                *(uint32_t*)(Cl + (size_t)z * SLOT + (size_t)(r + 8) * EDIM + col) = lw;
            } else {
                float bx = bias[col], by = bias[col + 1];
                *(float2*)(C + (size_t)r * EDIM + col) =
                    make_float2(acc[mt][nt][0] + bx, acc[mt][nt][1] + by);
                *(float2*)(C + (size_t)(r + 8) * EDIM + col) =
                    make_float2(acc[mt][nt][2] + bx, acc[mt][nt][3] + by);
            }
        }
    }
}

// ---------------------------------------------------------------------------
// Flash attention on HMMA (R13 version — measured 470us, tensor 75.7%).
// 4 warps x 32 q-rows (Br=128), Bc=64, fused per-16-key block, 3-stage
// ring, 2 CTAs/SM. q PRE-SCALED by log2(e) -> raw ex2.approx; softmax over
// UNSCALED scores (faithful reference bug), no running max. Row sums via
// tensor core (all-ones B operand in PV phase).
// ---------------------------------------------------------------------------
#define KROWB    144
#define KTILE    (64 * KROWB)                // 9216
#define QTILE    (128 * KROWB)               // 18432
#define FA_STAGE (4 * KTILE)                 // 36864
#define FA_STAGES 3
#define FA_SMEM  (FA_STAGES * FA_STAGE)      // 110592

__global__ __launch_bounds__(128, 2)
void flash_hmma(const __nv_bfloat16* __restrict__ ph, const __nv_bfloat16* __restrict__ pl,
                __nv_bfloat16* __restrict__ oh, __nv_bfloat16* __restrict__ ol)
{
    extern __shared__ char sm[];
    const uint32_t sb = smem_u32(sm);
    const int tid  = threadIdx.x;
    const int wid  = tid >> 5;
    const int lane = tid & 31;
    const int warp_m = wid * 32;

    const int qt = blockIdx.x;
    const int h  = blockIdx.y;
    const int b  = blockIdx.z;
    const size_t baseRow = (size_t)b * SEQ;
    const int hcol = h * HD;

    const __nv_bfloat16* qh = ph;
    const __nv_bfloat16* ql = pl;
    const __nv_bfloat16* kh = ph + SLOT;
    const __nv_bfloat16* kl = pl + SLOT;
    const __nv_bfloat16* vh = ph + 2 * SLOT;
    const __nv_bfloat16* vl = pl + 2 * SLOT;

    const uint32_t a_loff  = (uint32_t)(lane & 15) * KROWB + ((lane & 16) ? 16u : 0u);
    const uint32_t bk_loff = (uint32_t)((lane & 7) + ((lane & 16) ? 8 : 0)) * KROWB
                           + ((lane & 8) ? 16u : 0u);
    const uint32_t bv_loff = (uint32_t)((lane & 7) + ((lane & 8) ? 8 : 0)) * KROWB
                           + ((lane & 16) ? 16u : 0u);

    // ---- stage Q (hi at 0, lo at QTILE), pull A-fragments ----
    {
#pragma unroll
        for (int it = 0; it < 8; it++) {
            int c = tid + it * 128;          // 0..1023
            int row = c >> 3, ch = c & 7;
            uint32_t doff = (uint32_t)row * KROWB + (uint32_t)ch * 16;
            size_t ga = (baseRow + qt * 128 + row) * EDIM + hcol + ch * 8;
            cp16(sb + doff,         qh + ga);
            cp16(sb + QTILE + doff, ql + ga);
        }
        CP_COMMIT();
        CP_WAIT(0);
        __syncthreads();
    }
    uint32_t qfr[2][4][2][4];   // [split][kstep][mt][frag]
#pragma unroll
    for (int sp = 0; sp < 2; sp++)
#pragma unroll
        for (int ks = 0; ks < 4; ks++)
#pragma unroll
            for (int mt = 0; mt < 2; mt++)
                ldsm_x4(qfr[sp][ks][mt],
                        sb + sp * QTILE + (uint32_t)(warp_m + mt * 16) * KROWB
                             + ks * 32 + a_loff);
    __syncthreads();

    auto issue_kv = [&](int t) {
        const uint32_t base = sb + (uint32_t)(t % 3) * FA_STAGE;
#pragma unroll
        for (int it = 0; it < 4; it++) {
            int c = tid + it * 128;          // 0..511
            int row = c >> 3, ch = c & 7;
            uint32_t doff = (uint32_t)row * KROWB + (uint32_t)ch * 16;
            size_t ga = (baseRow + t * 64 + row) * EDIM + hcol + ch * 8;
            cp16(base + doff,             kh + ga);
            cp16(base + KTILE + doff,     kl + ga);
            cp16(base + 2 * KTILE + doff, vh + ga);
            cp16(base + 3 * KTILE + doff, vl + ga);
        }
        CP_COMMIT();
    };

    issue_kv(0);
    issue_kv(1);

    float Oa[2][8][4];
#pragma unroll
    for (int mt = 0; mt < 2; mt++)
#pragma unroll
        for (int i = 0; i < 8; i++)
#pragma unroll
            for (int c = 0; c < 4; c++) Oa[mt][i][c] = 0.f;
    float Osum[2][4];           // tensor-core row sums (cols all-equal)
#pragma unroll
    for (int mt = 0; mt < 2; mt++)
#pragma unroll
        for (int c = 0; c < 4; c++) Osum[mt][c] = 0.f;

    const uint32_t onesb[2] = {0x3F803F80u, 0x3F803F80u};  // bf16 1.0 x2

    const int NT = SEQ / 64;   // 32
    for (int t = 0; t < NT; t++) {
        if (t + 2 <= NT) { CP_WAIT(1); } else { CP_WAIT(0); }
        __syncthreads();
        if (t + 2 < NT) issue_kv(t + 2);

        const uint32_t bs = sb + (uint32_t)(t % 3) * FA_STAGE;

        // fused per-16-key block: QK -> ex2 -> pack -> PV (+ones sum)
#pragma unroll
        for (int ng = 0; ng < 4; ng++) {
            float S[2][2][4];
#pragma unroll
            for (int mt = 0; mt < 2; mt++)
#pragma unroll
                for (int tt = 0; tt < 2; tt++)
#pragma unroll
                    for (int c = 0; c < 4; c++) S[mt][tt][c] = 0.f;

#pragma unroll
            for (int ks = 0; ks < 4; ks++) {
                uint32_t b1[4], b2[4];
                uint32_t kb = bs + (uint32_t)(ng * 16) * KROWB + ks * 32 + bk_loff;
                ldsm_x4(b1, kb);
                ldsm_x4(b2, kb + KTILE);
#pragma unroll
                for (int mt = 0; mt < 2; mt++) {
                    mma16816(S[mt][0], qfr[0][ks][mt], &b1[0]);
                    mma16816(S[mt][1], qfr[0][ks][mt], &b1[2]);
                    mma16816(S[mt][0], qfr[0][ks][mt], &b2[0]);
                    mma16816(S[mt][1], qfr[0][ks][mt], &b2[2]);
                    mma16816(S[mt][0], qfr[1][ks][mt], &b1[0]);
                    mma16816(S[mt][1], qfr[1][ks][mt], &b1[2]);
                }
            }

            uint32_t p1[2][4], p2[2][4];
#pragma unroll
            for (int mt = 0; mt < 2; mt++) {
#pragma unroll
                for (int tt = 0; tt < 2; tt++) {
                    S[mt][tt][0] = ex2f(S[mt][tt][0]);
                    S[mt][tt][1] = ex2f(S[mt][tt][1]);
                    S[mt][tt][2] = ex2f(S[mt][tt][2]);
                    S[mt][tt][3] = ex2f(S[mt][tt][3]);
                }
#pragma unroll
                for (int tt = 0; tt < 2; tt++)
#pragma unroll
                    for (int hl = 0; hl < 2; hl++)
                        split_pair(S[mt][tt][2 * hl + 0], S[mt][tt][2 * hl + 1],
                                   p1[mt][tt * 2 + hl], p2[mt][tt * 2 + hl]);
                // row sums via tensor core (ones operand, no ldsm needed)
                mma16816(Osum[mt], p1[mt], onesb);
                mma16816(Osum[mt], p2[mt], onesb);
            }

#pragma unroll
            for (int dg = 0; dg < 4; dg++) {
                uint32_t v1[4], v2[4];
                uint32_t vb = bs + 2 * KTILE + (uint32_t)(ng * 16) * KROWB
                            + dg * 32 + bv_loff;
                ldsm_x4_t(v1, vb);
                ldsm_x4_t(v2, vb + KTILE);
#pragma unroll
                for (int mt = 0; mt < 2; mt++) {
                    mma16816(Oa[mt][dg * 2 + 0], p1[mt], &v1[0]);
                    mma16816(Oa[mt][dg * 2 + 1], p1[mt], &v1[2]);
                    mma16816(Oa[mt][dg * 2 + 0], p1[mt], &v2[0]);
                    mma16816(Oa[mt][dg * 2 + 1], p1[mt], &v2[2]);
                    mma16816(Oa[mt][dg * 2 + 0], p2[mt], &v1[0]);
                    mma16816(Oa[mt][dg * 2 + 1], p2[mt], &v1[2]);
                }
            }
        }
    }

    // ---- normalize & write split output into slot 0 of (oh, ol) ----
    // Osum[mt][0] = row (warp_m+mt*16+g) sum; Osum[mt][2] = row (+8) sum.
    const int g   = lane >> 2;
    const int tq2 = (lane & 3) * 2;
#pragma unroll
    for (int mt = 0; mt < 2; mt++) {
        const float inv0 = 1.0f / Osum[mt][0];
        const float inv1 = 1.0f / Osum[mt][2];
        const size_t r0 = (baseRow + qt * 128 + warp_m + mt * 16 + g) * EDIM + hcol;
        const size_t r1 = r0 + (size_t)8 * EDIM;
#pragma unroll
        for (int i = 0; i < 8; i++) {
            int d = i * 8 + tq2;
            uint32_t hw, lw;
            split_pair(Oa[mt][i][0] * inv0, Oa[mt][i][1] * inv0, hw, lw);
            *(uint32_t*)(oh + r0 + d) = hw;
            *(uint32_t*)(ol + r0 + d) = lw;
            split_pair(Oa[mt][i][2] * inv1, Oa[mt][i][3] * inv1, hw, lw);
            *(uint32_t*)(oh + r1 + d) = hw;
            *(uint32_t*)(ol + r1 + d) = lw;
        }
    }
}

// ---------------------------------------------------------------------------
extern "C" void kernel_launch(void* const* d_in, const int* in_sizes, int n_in,
                              void* d_out, int out_size)
{
    (void)in_sizes; (void)n_in; (void)out_size;

    const float* Q  = (const float*)d_in[0];
    const float* K  = (const float*)d_in[1];
    const float* V  = (const float*)d_in[2];
    const float* Wq = (const float*)d_in[3];
    const float* Wk = (const float*)d_in[4];
    const float* Wv = (const float*)d_in[5];
    const float* Wo = (const float*)d_in[6];
    const float* bo = (const float*)d_in[7];
    float* out = (float*)d_out;

    __nv_bfloat16 *xh, *xl, *phb, *plb, *wh, *wl;
    cudaGetSymbolAddress((void**)&xh, g_xh);
    cudaGetSymbolAddress((void**)&xl, g_xl);
    cudaGetSymbolAddress((void**)&phb, g_ph);
    cudaGetSymbolAddress((void**)&plb, g_pl);
    cudaGetSymbolAddress((void**)&wh, g_wh);
    cudaGetSymbolAddress((void**)&wl, g_wl);

    cudaFuncSetAttribute(gemm_hmma<true>,
                         cudaFuncAttributeMaxDynamicSharedMemorySize, GEMM_SMEM);
    cudaFuncSetAttribute(gemm_hmma<false>,
                         cudaFuncAttributeMaxDynamicSharedMemorySize, GEMM_SMEM);
    cudaFuncSetAttribute(flash_hmma,
                         cudaFuncAttributeMaxDynamicSharedMemorySize, FA_SMEM);

    const int nA4 = MTOT * EDIM / 4;
    const int nW4 = EDIM * EDIM / 4;

    split_in_kernel<<<dim3(nA4 / 256, 3), 256>>>(Q, K, V, xh, xl, nA4);
    split_w_kernel<<<dim3(nW4 / 256, 4), 256>>>(Wq, Wk, Wv, Wo, wh, wl, nW4);

    gemm_hmma<true><<<dim3(EDIM / 128, MTOT / 128, 3), 128, GEMM_SMEM>>>(
        xh, xl, wh, wl, nullptr, nullptr, phb, plb);

    flash_hmma<<<dim3(SEQ / 128, NH, NB), 128, FA_SMEM>>>(phb, plb, xh, xl);

    gemm_hmma<false><<<dim3(EDIM / 128, MTOT / 128, 1), 128, GEMM_SMEM>>>(
        xh, xl, wh + 3 * WSLOT, wl + 3 * WSLOT, bo, out, nullptr, nullptr);
}